// round 5
// baseline (speedup 1.0000x reference)
#include <cuda_runtime.h>

#define NCLS 19
#define CH   32
#define IN_H 128
#define IN_W 128
#define OUT_H 512
#define OUT_W 512
#define NB   4
#define HB   16   // histogram blocks per batch
#define GRID_MAIN (NB * 64 * 4)

// Device-global scratch (no allocations allowed in kernel_launch).
__device__ float    g_T[(size_t)NB * IN_H * IN_W * CH];  // transposed embedding (N,H,W,C)
__device__ float    g_S1[NB * NCLS * CH];                // per (n,k,c) sum
__device__ float    g_S2[NB * NCLS * CH];                // per (n,k,c) sum of squares
__device__ int      g_hist[NB][HB][NCLS];                // partial label histograms
__device__ unsigned g_done;

// ---------------------------------------------------------------------------
// Prep: (N,C,H,W)->(N,H,W,C) transpose + zero accumulators + label histogram.
__global__ void __launch_bounds__(1024) prep_kernel(const float* __restrict__ in,
                                                    const int* __restrict__ label) {
    __shared__ float tile[32][33];
    __shared__ int   whist[32][NCLS];

    const int n  = blockIdx.z;          // 4
    const int y  = blockIdx.y;          // 128
    const int xb = blockIdx.x * 32;     // 4 tiles along W
    const int tx = threadIdx.x;
    const int ty = threadIdx.y;
    const int tid = ty * 32 + tx;

    // transpose: read channel ty, x = xb+tx (coalesced)
    tile[ty][tx] = in[((((size_t)n * CH + ty) * IN_H + y) * IN_W) + xb + tx];

    // one block zeroes the global accumulators + done flag
    if (blockIdx.x == 3 && y == 127 && n == 3) {
        for (int i = tid; i < NB * NCLS * CH; i += 1024) { g_S1[i] = 0.f; g_S2[i] = 0.f; }
        if (tid == 0) g_done = 0u;
    }

    // HB blocks per batch build the label histogram (match_any, no atomics)
    if (blockIdx.x == 0 && y < HB) {
        const int w    = tid >> 5;
        const int lane = tid & 31;
        for (int i = lane; i < NCLS; i += 32) whist[w][i] = 0;
        __syncwarp();
        const int4* lp = (const int4*)(label + (size_t)n * OUT_H * OUT_W
                                             + (size_t)y * (OUT_H * OUT_W / HB));
        #pragma unroll
        for (int r = 0; r < 4; ++r) {
            int4 L = lp[r * 1024 + tid];           // coalesced
            int ks[4] = {L.x, L.y, L.z, L.w};
            #pragma unroll
            for (int j = 0; j < 4; ++j) {
                int k = (int)min((unsigned)ks[j], (unsigned)(NCLS - 1));
                unsigned m  = __match_any_sync(0xffffffffu, k);
                int leader  = __ffs(m) - 1;
                if (lane == leader) whist[w][k] += __popc(m);
            }
        }
        __syncthreads();   // block-uniform branch: legal
        if (tid < NCLS) {
            int c = 0;
            #pragma unroll
            for (int ww = 0; ww < 32; ++ww) c += whist[ww][tid];
            g_hist[n][y][tid] = c;
        }
    }

    __syncthreads();
    // write: x = xb+ty, channel tx (coalesced in c)
    g_T[((((size_t)n * IN_H + y) * IN_W) + xb + ty) * CH + tx] = tile[tx][ty];
}

// ---------------------------------------------------------------------------
// Main pass: warp = quarter of an output row (128 px), lane = channel.
// Two independent pixel streams per warp; per-warp float2 smem bins.
__global__ void __launch_bounds__(256, 5) main_kernel(const int* __restrict__ label,
                                                      float* __restrict__ out) {
    __shared__ __align__(16) unsigned char raw[8 * NCLS * CH * 8];  // 38912 B
    float2 (*s)[NCLS * CH] = reinterpret_cast<float2 (*)[NCLS * CH]>(raw);
    __shared__ unsigned s_last;

    const int tid  = threadIdx.x;
    const int w    = tid >> 5;
    const int lane = tid & 31;
    const int bx   = blockIdx.x;
    const int n    = bx >> 8;            // 4 batches
    const int rb   = (bx >> 2) & 63;     // 64 row-blocks
    const int q    = bx & 3;             // quarter of the row
    const int y    = rb * 8 + w;         // warp's output row
    const int t0   = q * 32;             // first 4-px group of this warp

    for (int i = tid; i < 8 * NCLS * CH; i += 256)
        ((float2*)raw)[i] = make_float2(0.f, 0.f);
    __syncthreads();

    // y interpolation (scale exactly 4, half-pixel sampling)
    const int   y0  = ((y + 2) >> 2) - 1;
    const float fy  = 0.125f + 0.25f * (float)((y + 2) & 3);
    const int   y0c = y0 < 0 ? 0 : y0;
    const int   y1c = (y0 + 1) > (IN_H - 1) ? (IN_H - 1) : (y0 + 1);

    const float* __restrict__ rowA = g_T + ((size_t)(n * IN_H + y0c) * IN_W) * CH + lane;
    const float* __restrict__ rowB = g_T + ((size_t)(n * IN_H + y1c) * IN_W) * CH + lane;
    const int4*  __restrict__ lab4 =
        (const int4*)(label + ((size_t)(n * OUT_H + y) * OUT_W));

    float2* __restrict__ sbl = s[w] + lane;

    auto loady = [&](int c) -> float {               // y-lerped, x-clamped column
        c = c < 0 ? 0 : (c > IN_W - 1 ? IN_W - 1 : c);
        float a = rowA[c * CH];
        float b = rowB[c * CH];
        return fmaf(fy, b - a, a);
    };
    auto bin = [&](int k, float v) {                 // k trusted in [0,19)
        float2* p = sbl + k * CH;
        float2 o = *p;
        o.x += v;
        o.y = fmaf(v, v, o.y);
        *p = o;
    };
    // group t: pixels 4t..4t+3 use columns (t-1,t) for px0,1 and (t,t+1) for px2,3.
    auto group = [&](int t, float yvA, float yvB, float yvC) {
        int4  L  = lab4[t];
        float d0 = yvB - yvA;
        float d1 = yvC - yvB;
        bin(L.x, fmaf(0.625f, d0, yvA));
        bin(L.y, fmaf(0.875f, d0, yvA));
        bin(L.z, fmaf(0.125f, d1, yvB));
        bin(L.w, fmaf(0.375f, d1, yvB));
    };

    // two independent streams: groups [t0, t0+16) and [t0+16, t0+32)
    int ta = t0, tb = t0 + 16;
    float aA = loady(ta - 1), aB = loady(ta);
    float bA = loady(tb - 1), bB = loady(tb);
    #pragma unroll 2
    for (int i = 0; i < 16; ++i) {
        float aC = loady(ta + 1);
        float bC = loady(tb + 1);
        group(ta, aA, aB, aC);
        group(tb, bA, bB, bC);
        aA = aB; aB = aC;
        bA = bB; bB = bC;
        ++ta; ++tb;
    }
    __syncthreads();

    // reduce 8 warp copies -> global atomics
    for (int i = tid; i < NCLS * CH; i += 256) {
        float a = 0.f, b = 0.f;
        #pragma unroll
        for (int ww = 0; ww < 8; ++ww) { float2 v = s[ww][i]; a += v.x; b += v.y; }
        atomicAdd(&g_S1[n * NCLS * CH + i], a);
        atomicAdd(&g_S2[n * NCLS * CH + i], b);
    }

    __threadfence();
    if (tid == 0) s_last = (atomicAdd(&g_done, 1u) == (unsigned)(gridDim.x - 1));
    __syncthreads();
    if (!s_last) return;

    // ---------------- epilogue (last CTA, reuses smem) ----------------
    struct Epi {
        float cnt[NB][NCLS];
        float mu[NB][NCLS][CH];
        float intra[NB][NCLS];
        float interp[NB][2];
        float nfg[NB];
        float l2i[NB];
    };
    Epi* e = reinterpret_cast<Epi*>(raw);

    if (tid < NB * NCLS) {
        int nn = tid / NCLS, k = tid % NCLS;
        int c = 0;
        #pragma unroll
        for (int h = 0; h < HB; ++h) c += g_hist[nn][h][k];
        e->cnt[nn][k] = (float)c;
    }
    __syncthreads();

    {   // per-class mean + intra (warp pair per batch)
        int nn = w >> 1, sub = w & 1;
        for (int k = sub; k < NCLS; k += 2) {
            float cn = e->cnt[nn][k];
            float s1 = __ldcg(&g_S1[nn * NCLS * CH + k * CH + lane]);
            float s2 = __ldcg(&g_S2[nn * NCLS * CH + k * CH + lane]);
            float m  = s1 / (cn + 1.0f);
            e->mu[nn][k][lane] = m;
            float t2 = s2 + m * fmaf(cn, m, -2.0f * s1);
            #pragma unroll
            for (int o = 16; o; o >>= 1) t2 += __shfl_xor_sync(0xffffffffu, t2, o);
            if (lane == 0) e->intra[nn][k] = t2 / ((float)CH * (cn + 1.0f));
        }
    }
    __syncthreads();

    if (tid < NB) {
        float nf = 0.f, li = 0.f;
        for (int k = 1; k < NCLS; ++k)
            if (e->cnt[tid][k] > 0.f) { nf += 1.f; li += e->intra[tid][k]; }
        e->nfg[tid] = nf;
        e->l2i[tid] = li / nf;
    }
    __syncthreads();

    {   // inter: masked pairwise mean-squared distances
        int nn = w >> 1, sub = w & 1;
        float acc = 0.f;
        for (int p = sub; p < NCLS * NCLS; p += 2) {
            int j = p / NCLS, k = p - j * NCLS;
            if (j >= 1 && k >= 1 && e->cnt[nn][j] > 0.f && e->cnt[nn][k] > 0.f) {
                float d = e->mu[nn][j][lane] - e->mu[nn][k][lane];
                acc = fmaf(d, d, acc);
            }
        }
        #pragma unroll
        for (int o = 16; o; o >>= 1) acc += __shfl_xor_sync(0xffffffffu, acc, o);
        if (lane == 0) e->interp[nn][sub] = acc / (float)CH;
    }
    __syncthreads();

    if (tid < NB) {
        float inter = e->interp[tid][0] + e->interp[tid][1];
        out[tid] = e->l2i[tid] - inter / (e->nfg[tid] * e->nfg[tid]);
    }
}

// ---------------------------------------------------------------------------
extern "C" void kernel_launch(void* const* d_in, const int* in_sizes, int n_in,
                              void* d_out, int out_size) {
    const float* emb   = (const float*)d_in[0];   // (4,32,128,128) f32
    const int*   label = (const int*)d_in[1];     // (4,512,512) int32
    float*       out   = (float*)d_out;           // (4,) f32

    prep_kernel<<<dim3(IN_W / 32, IN_H, NB), dim3(32, 32)>>>(emb, label);
    main_kernel<<<GRID_MAIN, 256>>>(label, out);
}

// round 6
// speedup vs baseline: 1.0240x; 1.0240x over previous
#include <cuda_runtime.h>

#define NCLS 19
#define CH   32
#define IN_H 128
#define IN_W 128
#define OUT_H 512
#define OUT_W 512
#define NB   4
#define HB   16   // histogram blocks per batch
#define GRID_MAIN (NB * 64 * 2)
#define PF   8    // column prefetch depth (register ring)

// Device-global scratch (no allocations allowed in kernel_launch).
__device__ float    g_T[(size_t)NB * IN_H * IN_W * CH];  // transposed embedding (N,H,W,C)
__device__ float    g_S1[NB * NCLS * CH];                // per (n,k,c) sum
__device__ float    g_S2[NB * NCLS * CH];                // per (n,k,c) sum of squares
__device__ int      g_hist[NB][HB][NCLS];                // partial label histograms
__device__ unsigned g_done;

// ---------------------------------------------------------------------------
// Prep: (N,C,H,W)->(N,H,W,C) transpose + zero accumulators + label histogram.
__global__ void __launch_bounds__(1024) prep_kernel(const float* __restrict__ in,
                                                    const int* __restrict__ label) {
    __shared__ float tile[32][33];
    __shared__ int   whist[32][NCLS];

    const int n  = blockIdx.z;          // 4
    const int y  = blockIdx.y;          // 128
    const int xb = blockIdx.x * 32;     // 4 tiles along W
    const int tx = threadIdx.x;
    const int ty = threadIdx.y;
    const int tid = ty * 32 + tx;

    // transpose: read channel ty, x = xb+tx (coalesced)
    tile[ty][tx] = in[((((size_t)n * CH + ty) * IN_H + y) * IN_W) + xb + tx];

    // one block zeroes the global accumulators + done flag
    if (blockIdx.x == 3 && y == 127 && n == 3) {
        for (int i = tid; i < NB * NCLS * CH; i += 1024) { g_S1[i] = 0.f; g_S2[i] = 0.f; }
        if (tid == 0) g_done = 0u;
    }

    // HB blocks per batch build the label histogram (match_any, no atomics)
    if (blockIdx.x == 0 && y < HB) {
        const int w    = tid >> 5;
        const int lane = tid & 31;
        for (int i = lane; i < NCLS; i += 32) whist[w][i] = 0;
        __syncwarp();
        const int4* lp = (const int4*)(label + (size_t)n * OUT_H * OUT_W
                                             + (size_t)y * (OUT_H * OUT_W / HB));
        #pragma unroll
        for (int r = 0; r < 4; ++r) {
            int4 L = lp[r * 1024 + tid];           // coalesced
            int ks[4] = {L.x, L.y, L.z, L.w};
            #pragma unroll
            for (int j = 0; j < 4; ++j) {
                int k = (int)min((unsigned)ks[j], (unsigned)(NCLS - 1));
                unsigned m  = __match_any_sync(0xffffffffu, k);
                int leader  = __ffs(m) - 1;
                if (lane == leader) whist[w][k] += __popc(m);
            }
        }
        __syncthreads();   // block-uniform branch: legal
        if (tid < NCLS) {
            int c = 0;
            #pragma unroll
            for (int ww = 0; ww < 32; ++ww) c += whist[ww][tid];
            g_hist[n][y][tid] = c;
        }
    }

    __syncthreads();
    // write: x = xb+ty, channel tx (coalesced in c)
    g_T[((((size_t)n * IN_H + y) * IN_W) + xb + ty) * CH + tx] = tile[tx][ty];
}

// ---------------------------------------------------------------------------
// Main pass: warp = half an output row (256 px = 64 groups), lane = channel.
// Software-pipelined column loads (register ring, depth PF) hide L2 latency.
__global__ void __launch_bounds__(256) main_kernel(const int* __restrict__ label,
                                                   float* __restrict__ out) {
    __shared__ __align__(16) unsigned char raw[8 * NCLS * CH * 8];  // 38912 B
    float2 (*s)[NCLS * CH] = reinterpret_cast<float2 (*)[NCLS * CH]>(raw);
    __shared__ unsigned s_last;

    const int tid  = threadIdx.x;
    const int w    = tid >> 5;
    const int lane = tid & 31;
    const int bx   = blockIdx.x;
    const int n    = bx >> 7;            // 4 batches
    const int rem  = bx & 127;
    const int rb   = rem >> 1;           // 64 row-blocks
    const int half = rem & 1;            // left / right half of the row
    const int y    = rb * 8 + w;         // warp's output row
    const int g0   = half * 64;          // first 4-px group of this warp

    for (int i = tid; i < 8 * NCLS * CH; i += 256)
        ((float2*)raw)[i] = make_float2(0.f, 0.f);
    __syncthreads();

    // y interpolation (scale exactly 4, half-pixel sampling)
    const int   y0  = ((y + 2) >> 2) - 1;
    const float fy  = 0.125f + 0.25f * (float)((y + 2) & 3);
    const int   y0c = y0 < 0 ? 0 : y0;
    const int   y1c = (y0 + 1) > (IN_H - 1) ? (IN_H - 1) : (y0 + 1);

    const float* __restrict__ rowA = g_T + ((size_t)(n * IN_H + y0c) * IN_W) * CH + lane;
    const float* __restrict__ rowB = g_T + ((size_t)(n * IN_H + y1c) * IN_W) * CH + lane;
    const int4*  __restrict__ lab4 =
        (const int4*)(label + ((size_t)(n * OUT_H + y) * OUT_W));

    float2* __restrict__ sbl = s[w] + lane;

    auto clampc = [&](int c) -> int {
        return c < 0 ? 0 : (c > IN_W - 1 ? IN_W - 1 : c);
    };
    auto bin = [&](int k, float v) {                 // k trusted in [0,19)
        float2* p = sbl + k * CH;
        float2 o = *p;
        o.x += v;
        o.y = fmaf(v, v, o.y);
        *p = o;
    };

    // column ring buffer: relative column r (= absolute g0-1+i) lives in slot (r+1)%PF
    float cA[PF], cB[PF];
    #pragma unroll
    for (int i = 0; i < PF; ++i) {
        int c = clampc(g0 - 1 + i);
        cA[i] = rowA[c * CH];
        cB[i] = rowB[c * CH];
    }
    float yvA = fmaf(fy, cB[0] - cA[0], cA[0]);   // column g0-1
    float yvB = fmaf(fy, cB[1] - cA[1], cA[1]);   // column g0

    // 64 groups; group g0+t: px 0,1 use (colA=t-1,colB=t); px 2,3 use (t,t+1)
    #pragma unroll 8
    for (int t = 0; t < 64; ++t) {
        const int slot = (t + 2) % PF;            // holds relative column t+1
        float yvC = fmaf(fy, cB[slot] - cA[slot], cA[slot]);
        {   // prefetch relative column t+PF-1 into slot t%PF (old col t-1, already lerped)
            int c = clampc(g0 + t + PF - 1);
            cA[t % PF] = rowA[c * CH];
            cB[t % PF] = rowB[c * CH];
        }
        int4  L  = lab4[g0 + t];
        float d0 = yvB - yvA;
        float d1 = yvC - yvB;
        bin(L.x, fmaf(0.625f, d0, yvA));
        bin(L.y, fmaf(0.875f, d0, yvA));
        bin(L.z, fmaf(0.125f, d1, yvB));
        bin(L.w, fmaf(0.375f, d1, yvB));
        yvA = yvB; yvB = yvC;
    }
    __syncthreads();

    // reduce 8 warp copies -> global atomics
    for (int i = tid; i < NCLS * CH; i += 256) {
        float a = 0.f, b = 0.f;
        #pragma unroll
        for (int ww = 0; ww < 8; ++ww) { float2 v = s[ww][i]; a += v.x; b += v.y; }
        atomicAdd(&g_S1[n * NCLS * CH + i], a);
        atomicAdd(&g_S2[n * NCLS * CH + i], b);
    }

    __threadfence();
    if (tid == 0) s_last = (atomicAdd(&g_done, 1u) == (unsigned)(gridDim.x - 1));
    __syncthreads();
    if (!s_last) return;

    // ---------------- epilogue (last CTA, reuses smem) ----------------
    struct Epi {
        float cnt[NB][NCLS];
        float mu[NB][NCLS][CH];
        float intra[NB][NCLS];
        float interp[NB][2];
        float nfg[NB];
        float l2i[NB];
    };
    Epi* e = reinterpret_cast<Epi*>(raw);

    if (tid < NB * NCLS) {
        int nn = tid / NCLS, k = tid % NCLS;
        int c = 0;
        #pragma unroll
        for (int h = 0; h < HB; ++h) c += g_hist[nn][h][k];
        e->cnt[nn][k] = (float)c;
    }
    __syncthreads();

    {   // per-class mean + intra (warp pair per batch)
        int nn = w >> 1, sub = w & 1;
        for (int k = sub; k < NCLS; k += 2) {
            float cn = e->cnt[nn][k];
            float s1 = __ldcg(&g_S1[nn * NCLS * CH + k * CH + lane]);
            float s2 = __ldcg(&g_S2[nn * NCLS * CH + k * CH + lane]);
            float m  = s1 / (cn + 1.0f);
            e->mu[nn][k][lane] = m;
            float t2 = s2 + m * fmaf(cn, m, -2.0f * s1);
            #pragma unroll
            for (int o = 16; o; o >>= 1) t2 += __shfl_xor_sync(0xffffffffu, t2, o);
            if (lane == 0) e->intra[nn][k] = t2 / ((float)CH * (cn + 1.0f));
        }
    }
    __syncthreads();

    if (tid < NB) {
        float nf = 0.f, li = 0.f;
        for (int k = 1; k < NCLS; ++k)
            if (e->cnt[tid][k] > 0.f) { nf += 1.f; li += e->intra[tid][k]; }
        e->nfg[tid] = nf;
        e->l2i[tid] = li / nf;
    }
    __syncthreads();

    {   // inter: masked pairwise mean-squared distances
        int nn = w >> 1, sub = w & 1;
        float acc = 0.f;
        for (int p = sub; p < NCLS * NCLS; p += 2) {
            int j = p / NCLS, k = p - j * NCLS;
            if (j >= 1 && k >= 1 && e->cnt[nn][j] > 0.f && e->cnt[nn][k] > 0.f) {
                float d = e->mu[nn][j][lane] - e->mu[nn][k][lane];
                acc = fmaf(d, d, acc);
            }
        }
        #pragma unroll
        for (int o = 16; o; o >>= 1) acc += __shfl_xor_sync(0xffffffffu, acc, o);
        if (lane == 0) e->interp[nn][sub] = acc / (float)CH;
    }
    __syncthreads();

    if (tid < NB) {
        float inter = e->interp[tid][0] + e->interp[tid][1];
        out[tid] = e->l2i[tid] - inter / (e->nfg[tid] * e->nfg[tid]);
    }
}

// ---------------------------------------------------------------------------
extern "C" void kernel_launch(void* const* d_in, const int* in_sizes, int n_in,
                              void* d_out, int out_size) {
    const float* emb   = (const float*)d_in[0];   // (4,32,128,128) f32
    const int*   label = (const int*)d_in[1];     // (4,512,512) int32
    float*       out   = (float*)d_out;           // (4,) f32

    prep_kernel<<<dim3(IN_W / 32, IN_H, NB), dim3(32, 32)>>>(emb, label);
    main_kernel<<<GRID_MAIN, 256>>>(label, out);
}

// round 7
// speedup vs baseline: 1.0391x; 1.0148x over previous
#include <cuda_runtime.h>

#define NCLS 19
#define CH   32
#define IN_H 128
#define IN_W 128
#define OUT_H 512
#define OUT_W 512
#define NB   4
#define HB   16   // histogram blocks per batch
#define GRID_MAIN (NB * 64 * 2)
#define PF   8    // column prefetch depth (register ring)

// Device-global scratch (no allocations allowed in kernel_launch).
__device__ float    g_T[(size_t)NB * IN_H * IN_W * CH];  // transposed embedding (N,H,W,C)
__device__ float    g_S1[NB * NCLS * CH];                // per (n,k,c) sum
__device__ float    g_S2[NB * NCLS * CH];                // per (n,k,c) sum of squares
__device__ int      g_hist[NB][HB][NCLS];                // partial label histograms
__device__ unsigned g_done;

// ---------------------------------------------------------------------------
// Prep: (N,C,H,W)->(N,H,W,C) transpose + zero accumulators + label histogram.
__global__ void __launch_bounds__(1024) prep_kernel(const float* __restrict__ in,
                                                    const int* __restrict__ label) {
    __shared__ float tile[32][33];
    __shared__ int   whist[32][NCLS];

    const int n  = blockIdx.z;          // 4
    const int y  = blockIdx.y;          // 128
    const int xb = blockIdx.x * 32;     // 4 tiles along W
    const int tx = threadIdx.x;
    const int ty = threadIdx.y;
    const int tid = ty * 32 + tx;

    // transpose: read channel ty, x = xb+tx (coalesced)
    tile[ty][tx] = in[((((size_t)n * CH + ty) * IN_H + y) * IN_W) + xb + tx];

    // one block zeroes the global accumulators + done flag
    if (blockIdx.x == 3 && y == 127 && n == 3) {
        for (int i = tid; i < NB * NCLS * CH; i += 1024) { g_S1[i] = 0.f; g_S2[i] = 0.f; }
        if (tid == 0) g_done = 0u;
    }

    // HB blocks per batch build the label histogram (match_any, no atomics)
    if (blockIdx.x == 0 && y < HB) {
        const int w    = tid >> 5;
        const int lane = tid & 31;
        for (int i = lane; i < NCLS; i += 32) whist[w][i] = 0;
        __syncwarp();
        const int4* lp = (const int4*)(label + (size_t)n * OUT_H * OUT_W
                                             + (size_t)y * (OUT_H * OUT_W / HB));
        #pragma unroll
        for (int r = 0; r < 4; ++r) {
            int4 L = lp[r * 1024 + tid];           // coalesced
            int ks[4] = {L.x, L.y, L.z, L.w};
            #pragma unroll
            for (int j = 0; j < 4; ++j) {
                int k = (int)min((unsigned)ks[j], (unsigned)(NCLS - 1));
                unsigned m  = __match_any_sync(0xffffffffu, k);
                int leader  = __ffs(m) - 1;
                if (lane == leader) whist[w][k] += __popc(m);
            }
        }
        __syncthreads();   // block-uniform branch: legal
        if (tid < NCLS) {
            int c = 0;
            #pragma unroll
            for (int ww = 0; ww < 32; ++ww) c += whist[ww][tid];
            g_hist[n][y][tid] = c;
        }
    }

    __syncthreads();
    // write: x = xb+ty, channel tx (coalesced in c)
    g_T[((((size_t)n * IN_H + y) * IN_W) + xb + ty) * CH + tx] = tile[tx][ty];
}

// ---------------------------------------------------------------------------
// Main pass: warp = half an output row (256 px = 64 groups), lane = channel.
// Labels staged through smem (bulk coalesced load); g_T via register ring.
__global__ void __launch_bounds__(256) main_kernel(const int* __restrict__ label,
                                                   float* __restrict__ out) {
    __shared__ __align__(16) unsigned char raw[8 * NCLS * CH * 8];  // 38912 B
    __shared__ __align__(16) int4 slab[8][64];                      // 8192 B labels
    float2 (*s)[NCLS * CH] = reinterpret_cast<float2 (*)[NCLS * CH]>(raw);
    __shared__ unsigned s_last;

    const int tid  = threadIdx.x;
    const int w    = tid >> 5;
    const int lane = tid & 31;
    const int bx   = blockIdx.x;
    const int n    = bx >> 7;            // 4 batches
    const int rem  = bx & 127;
    const int rb   = rem >> 1;           // 64 row-blocks
    const int half = rem & 1;            // left / right half of the row
    const int y    = rb * 8 + w;         // warp's output row
    const int g0   = half * 64;          // first 4-px group of this warp

    // stage this warp's 256 labels into smem (2 coalesced LDG.128 per lane)
    {
        const int4* lp = (const int4*)(label + ((size_t)(n * OUT_H + y) * OUT_W)) + g0;
        slab[w][lane]      = lp[lane];
        slab[w][lane + 32] = lp[lane + 32];
    }

    for (int i = tid; i < 8 * NCLS * CH; i += 256)
        ((float2*)raw)[i] = make_float2(0.f, 0.f);
    __syncthreads();

    // y interpolation (scale exactly 4, half-pixel sampling)
    const int   y0  = ((y + 2) >> 2) - 1;
    const float fy  = 0.125f + 0.25f * (float)((y + 2) & 3);
    const int   y0c = y0 < 0 ? 0 : y0;
    const int   y1c = (y0 + 1) > (IN_H - 1) ? (IN_H - 1) : (y0 + 1);

    const float* __restrict__ rowA = g_T + ((size_t)(n * IN_H + y0c) * IN_W) * CH + lane;
    const float* __restrict__ rowB = g_T + ((size_t)(n * IN_H + y1c) * IN_W) * CH + lane;

    float2* __restrict__ sbl = s[w] + lane;

    auto clampc = [&](int c) -> int {
        return c < 0 ? 0 : (c > IN_W - 1 ? IN_W - 1 : c);
    };
    auto bin = [&](int k, float v) {                 // k trusted in [0,19)
        float2* p = sbl + k * CH;
        float2 o = *p;
        o.x += v;
        o.y = fmaf(v, v, o.y);
        *p = o;
    };

    // column ring buffer: relative column r (= absolute g0-1+i) lives in slot (r+1)%PF
    float cA[PF], cB[PF];
    #pragma unroll
    for (int i = 0; i < PF; ++i) {
        int c = clampc(g0 - 1 + i);
        cA[i] = rowA[c * CH];
        cB[i] = rowB[c * CH];
    }
    float yvA = fmaf(fy, cB[0] - cA[0], cA[0]);   // column g0-1
    float yvB = fmaf(fy, cB[1] - cA[1], cA[1]);   // column g0

    int4 Lc = slab[w][0];                          // current group labels

    // 64 groups; group g0+t: px 0,1 use (colA=t-1,colB=t); px 2,3 use (t,t+1)
    #pragma unroll 8
    for (int t = 0; t < 64; ++t) {
        int4 Ln;
        if (t < 63) Ln = slab[w][t + 1];           // one-group label lookahead
        const int slot = (t + 2) % PF;             // holds relative column t+1
        float yvC = fmaf(fy, cB[slot] - cA[slot], cA[slot]);
        {   // prefetch relative column t+PF-1 into slot t%PF (old col t-1, already lerped)
            int c = clampc(g0 + t + PF - 1);
            cA[t % PF] = rowA[c * CH];
            cB[t % PF] = rowB[c * CH];
        }
        float d0 = yvB - yvA;
        float d1 = yvC - yvB;
        bin(Lc.x, fmaf(0.625f, d0, yvA));
        bin(Lc.y, fmaf(0.875f, d0, yvA));
        bin(Lc.z, fmaf(0.125f, d1, yvB));
        bin(Lc.w, fmaf(0.375f, d1, yvB));
        yvA = yvB; yvB = yvC;
        Lc = Ln;
    }
    __syncthreads();

    // reduce 8 warp copies -> global atomics
    for (int i = tid; i < NCLS * CH; i += 256) {
        float a = 0.f, b = 0.f;
        #pragma unroll
        for (int ww = 0; ww < 8; ++ww) { float2 v = s[ww][i]; a += v.x; b += v.y; }
        atomicAdd(&g_S1[n * NCLS * CH + i], a);
        atomicAdd(&g_S2[n * NCLS * CH + i], b);
    }

    __threadfence();
    if (tid == 0) s_last = (atomicAdd(&g_done, 1u) == (unsigned)(gridDim.x - 1));
    __syncthreads();
    if (!s_last) return;

    // ---------------- epilogue (last CTA, reuses smem) ----------------
    struct Epi {
        float cnt[NB][NCLS];
        float mu[NB][NCLS][CH];
        float intra[NB][NCLS];
        float interp[NB][2];
        float nfg[NB];
        float l2i[NB];
    };
    Epi* e = reinterpret_cast<Epi*>(raw);

    if (tid < NB * NCLS) {
        int nn = tid / NCLS, k = tid % NCLS;
        int c = 0;
        #pragma unroll
        for (int h = 0; h < HB; ++h) c += g_hist[nn][h][k];
        e->cnt[nn][k] = (float)c;
    }
    __syncthreads();

    {   // per-class mean + intra (warp pair per batch)
        int nn = w >> 1, sub = w & 1;
        for (int k = sub; k < NCLS; k += 2) {
            float cn = e->cnt[nn][k];
            float s1 = __ldcg(&g_S1[nn * NCLS * CH + k * CH + lane]);
            float s2 = __ldcg(&g_S2[nn * NCLS * CH + k * CH + lane]);
            float m  = s1 / (cn + 1.0f);
            e->mu[nn][k][lane] = m;
            float t2 = s2 + m * fmaf(cn, m, -2.0f * s1);
            #pragma unroll
            for (int o = 16; o; o >>= 1) t2 += __shfl_xor_sync(0xffffffffu, t2, o);
            if (lane == 0) e->intra[nn][k] = t2 / ((float)CH * (cn + 1.0f));
        }
    }
    __syncthreads();

    if (tid < NB) {
        float nf = 0.f, li = 0.f;
        for (int k = 1; k < NCLS; ++k)
            if (e->cnt[tid][k] > 0.f) { nf += 1.f; li += e->intra[tid][k]; }
        e->nfg[tid] = nf;
        e->l2i[tid] = li / nf;
    }
    __syncthreads();

    {   // inter: masked pairwise mean-squared distances
        int nn = w >> 1, sub = w & 1;
        float acc = 0.f;
        for (int p = sub; p < NCLS * NCLS; p += 2) {
            int j = p / NCLS, k = p - j * NCLS;
            if (j >= 1 && k >= 1 && e->cnt[nn][j] > 0.f && e->cnt[nn][k] > 0.f) {
                float d = e->mu[nn][j][lane] - e->mu[nn][k][lane];
                acc = fmaf(d, d, acc);
            }
        }
        #pragma unroll
        for (int o = 16; o; o >>= 1) acc += __shfl_xor_sync(0xffffffffu, acc, o);
        if (lane == 0) e->interp[nn][sub] = acc / (float)CH;
    }
    __syncthreads();

    if (tid < NB) {
        float inter = e->interp[tid][0] + e->interp[tid][1];
        out[tid] = e->l2i[tid] - inter / (e->nfg[tid] * e->nfg[tid]);
    }
}

// ---------------------------------------------------------------------------
extern "C" void kernel_launch(void* const* d_in, const int* in_sizes, int n_in,
                              void* d_out, int out_size) {
    const float* emb   = (const float*)d_in[0];   // (4,32,128,128) f32
    const int*   label = (const int*)d_in[1];     // (4,512,512) int32
    float*       out   = (float*)d_out;           // (4,) f32

    prep_kernel<<<dim3(IN_W / 32, IN_H, NB), dim3(32, 32)>>>(emb, label);
    main_kernel<<<GRID_MAIN, 256>>>(label, out);
}

// round 8
// speedup vs baseline: 1.0512x; 1.0116x over previous
#include <cuda_runtime.h>

#define NCLS 19
#define CH   32
#define IN_H 128
#define IN_W 128
#define OUT_H 512
#define OUT_W 512
#define NB   4
#define HB   16   // histogram blocks per batch
#define GRID_MAIN (NB * 64 * 2)

// Device-global scratch (no allocations allowed in kernel_launch).
__device__ float    g_T[(size_t)NB * IN_H * IN_W * CH];  // transposed embedding (N,H,W,C)
__device__ float    g_S1[NB * NCLS * CH];                // per (n,k,c) sum
__device__ float    g_S2[NB * NCLS * CH];                // per (n,k,c) sum of squares
__device__ int      g_hist[NB][HB][NCLS];                // partial label histograms
__device__ unsigned g_done;

// ---------------------------------------------------------------------------
// Prep: (N,C,H,W)->(N,H,W,C) transpose + zero accumulators + label histogram.
__global__ void __launch_bounds__(1024) prep_kernel(const float* __restrict__ in,
                                                    const int* __restrict__ label) {
    __shared__ float tile[32][33];
    __shared__ int   whist[32][NCLS];

    const int n  = blockIdx.z;          // 4
    const int y  = blockIdx.y;          // 128
    const int xb = blockIdx.x * 32;     // 4 tiles along W
    const int tx = threadIdx.x;
    const int ty = threadIdx.y;
    const int tid = ty * 32 + tx;

    // transpose: read channel ty, x = xb+tx (coalesced)
    tile[ty][tx] = in[((((size_t)n * CH + ty) * IN_H + y) * IN_W) + xb + tx];

    // one block zeroes the global accumulators + done flag
    if (blockIdx.x == 3 && y == 127 && n == 3) {
        for (int i = tid; i < NB * NCLS * CH; i += 1024) { g_S1[i] = 0.f; g_S2[i] = 0.f; }
        if (tid == 0) g_done = 0u;
    }

    // HB blocks per batch build the label histogram (match_any, no atomics)
    if (blockIdx.x == 0 && y < HB) {
        const int w    = tid >> 5;
        const int lane = tid & 31;
        for (int i = lane; i < NCLS; i += 32) whist[w][i] = 0;
        __syncwarp();
        const int4* lp = (const int4*)(label + (size_t)n * OUT_H * OUT_W
                                             + (size_t)y * (OUT_H * OUT_W / HB));
        #pragma unroll
        for (int r = 0; r < 4; ++r) {
            int4 L = lp[r * 1024 + tid];           // coalesced
            int ks[4] = {L.x, L.y, L.z, L.w};
            #pragma unroll
            for (int j = 0; j < 4; ++j) {
                int k = (int)min((unsigned)ks[j], (unsigned)(NCLS - 1));
                unsigned m  = __match_any_sync(0xffffffffu, k);
                int leader  = __ffs(m) - 1;
                if (lane == leader) whist[w][k] += __popc(m);
            }
        }
        __syncthreads();   // block-uniform branch: legal
        if (tid < NCLS) {
            int c = 0;
            #pragma unroll
            for (int ww = 0; ww < 32; ++ww) c += whist[ww][tid];
            g_hist[n][y][tid] = c;
        }
    }

    __syncthreads();
    // write: x = xb+ty, channel tx (coalesced in c)
    g_T[((((size_t)n * IN_H + y) * IN_W) + xb + ty) * CH + tx] = tile[tx][ty];
}

// ---------------------------------------------------------------------------
// Main pass: warp = half an output row (256 px = 64 groups), lane = channel.
// Minimal-instruction hot loop: edge cases peeled, pointers incremented.
__global__ void __launch_bounds__(256) main_kernel(const int* __restrict__ label,
                                                   float* __restrict__ out) {
    __shared__ __align__(16) unsigned char raw[8 * NCLS * CH * 8];  // 38912 B
    __shared__ __align__(16) int4 slab[8][64];                      // 8192 B labels
    float2 (*s)[NCLS * CH] = reinterpret_cast<float2 (*)[NCLS * CH]>(raw);
    __shared__ unsigned s_last;

    const int tid  = threadIdx.x;
    const int w    = tid >> 5;
    const int lane = tid & 31;
    const int bx   = blockIdx.x;
    const int n    = bx >> 7;            // 4 batches
    const int rem  = bx & 127;
    const int rb   = rem >> 1;           // 64 row-blocks
    const int half = rem & 1;            // left / right half of the row
    const int y    = rb * 8 + w;         // warp's output row
    const int g0   = half * 64;          // first 4-px group of this warp

    // stage this warp's 256 labels into smem (2 coalesced LDG.128 per lane)
    {
        const int4* lp = (const int4*)(label + ((size_t)(n * OUT_H + y) * OUT_W)) + g0;
        slab[w][lane]      = lp[lane];
        slab[w][lane + 32] = lp[lane + 32];
    }

    for (int i = tid; i < 8 * NCLS * CH / 2; i += 256)
        ((float4*)raw)[i] = make_float4(0.f, 0.f, 0.f, 0.f);
    __syncthreads();

    // y interpolation (scale exactly 4, half-pixel sampling)
    const int   y0  = ((y + 2) >> 2) - 1;
    const float fy  = 0.125f + 0.25f * (float)((y + 2) & 3);
    const int   y0c = y0 < 0 ? 0 : y0;
    const int   y1c = (y0 + 1) > (IN_H - 1) ? (IN_H - 1) : (y0 + 1);

    const float* __restrict__ rowA = g_T + ((size_t)(n * IN_H + y0c) * IN_W) * CH + lane;
    const float* __restrict__ rowB = g_T + ((size_t)(n * IN_H + y1c) * IN_W) * CH + lane;

    float2* __restrict__ sbl = s[w] + lane;

    auto bin = [&](int k, float v) {                 // k trusted in [0,19)
        float2* p = sbl + k * CH;
        float2 o = *p;
        o.x += v;
        o.y = fmaf(v, v, o.y);
        *p = o;
    };

    // prologue: yvB = column g0; yvA = column g0-1 (clamped for half 0)
    const float* pA = rowA + g0 * CH;    // points at column for yvB initially
    const float* pB = rowB + g0 * CH;
    float a0 = pA[0], b0 = pB[0];
    float yvB = fmaf(fy, b0 - a0, a0);
    float yvA;
    if (half) {
        float a1 = pA[-CH], b1 = pB[-CH];
        yvA = fmaf(fy, b1 - a1, a1);
    } else {
        yvA = yvB;                        // column -1 clamps to column 0
    }
    pA += CH; pB += CH;                   // now at column g0+1 (first yvC)

    // 63 clean groups (rel t = 0..62); group g0+t uses labels slab[w][t]
    #pragma unroll 4
    for (int t = 0; t < 63; ++t) {
        float a = pA[0], b = pB[0];
        pA += CH; pB += CH;
        float yvC = fmaf(fy, b - a, a);
        int4  L   = slab[w][t];
        float d0  = yvB - yvA;
        float d1  = yvC - yvB;
        bin(L.x, fmaf(0.625f, d0, yvA));
        bin(L.y, fmaf(0.875f, d0, yvA));
        bin(L.z, fmaf(0.125f, d1, yvB));
        bin(L.w, fmaf(0.375f, d1, yvB));
        yvA = yvB; yvB = yvC;
    }
    {   // final group (rel t = 63): half 0 loads col 64; half 1 clamps col 128
        float yvC;
        if (!half) {
            float a = pA[0], b = pB[0];
            yvC = fmaf(fy, b - a, a);
        } else {
            yvC = yvB;
        }
        int4  L  = slab[w][63];
        float d0 = yvB - yvA;
        float d1 = yvC - yvB;
        bin(L.x, fmaf(0.625f, d0, yvA));
        bin(L.y, fmaf(0.875f, d0, yvA));
        bin(L.z, fmaf(0.125f, d1, yvB));
        bin(L.w, fmaf(0.375f, d1, yvB));
    }
    __syncthreads();

    // reduce 8 warp copies -> global atomics
    for (int i = tid; i < NCLS * CH; i += 256) {
        float a = 0.f, b = 0.f;
        #pragma unroll
        for (int ww = 0; ww < 8; ++ww) { float2 v = s[ww][i]; a += v.x; b += v.y; }
        atomicAdd(&g_S1[n * NCLS * CH + i], a);
        atomicAdd(&g_S2[n * NCLS * CH + i], b);
    }

    __threadfence();
    if (tid == 0) s_last = (atomicAdd(&g_done, 1u) == (unsigned)(gridDim.x - 1));
    __syncthreads();
    if (!s_last) return;

    // ---------------- epilogue (last CTA, reuses smem) ----------------
    struct Epi {
        float cnt[NB][NCLS];
        float mu[NB][NCLS][CH];
        float intra[NB][NCLS];
        float interp[NB][2];
        float nfg[NB];
        float l2i[NB];
    };
    Epi* e = reinterpret_cast<Epi*>(raw);

    if (tid < NB * NCLS) {
        int nn = tid / NCLS, k = tid % NCLS;
        int c = 0;
        #pragma unroll
        for (int h = 0; h < HB; ++h) c += g_hist[nn][h][k];
        e->cnt[nn][k] = (float)c;
    }
    __syncthreads();

    {   // per-class mean + intra (warp pair per batch)
        int nn = w >> 1, sub = w & 1;
        for (int k = sub; k < NCLS; k += 2) {
            float cn = e->cnt[nn][k];
            float s1 = __ldcg(&g_S1[nn * NCLS * CH + k * CH + lane]);
            float s2 = __ldcg(&g_S2[nn * NCLS * CH + k * CH + lane]);
            float m  = s1 / (cn + 1.0f);
            e->mu[nn][k][lane] = m;
            float t2 = s2 + m * fmaf(cn, m, -2.0f * s1);
            #pragma unroll
            for (int o = 16; o; o >>= 1) t2 += __shfl_xor_sync(0xffffffffu, t2, o);
            if (lane == 0) e->intra[nn][k] = t2 / ((float)CH * (cn + 1.0f));
        }
    }
    __syncthreads();

    if (tid < NB) {
        float nf = 0.f, li = 0.f;
        for (int k = 1; k < NCLS; ++k)
            if (e->cnt[tid][k] > 0.f) { nf += 1.f; li += e->intra[tid][k]; }
        e->nfg[tid] = nf;
        e->l2i[tid] = li / nf;
    }
    __syncthreads();

    {   // inter: masked pairwise mean-squared distances
        int nn = w >> 1, sub = w & 1;
        float acc = 0.f;
        for (int p = sub; p < NCLS * NCLS; p += 2) {
            int j = p / NCLS, k = p - j * NCLS;
            if (j >= 1 && k >= 1 && e->cnt[nn][j] > 0.f && e->cnt[nn][k] > 0.f) {
                float d = e->mu[nn][j][lane] - e->mu[nn][k][lane];
                acc = fmaf(d, d, acc);
            }
        }
        #pragma unroll
        for (int o = 16; o; o >>= 1) acc += __shfl_xor_sync(0xffffffffu, acc, o);
        if (lane == 0) e->interp[nn][sub] = acc / (float)CH;
    }
    __syncthreads();

    if (tid < NB) {
        float inter = e->interp[tid][0] + e->interp[tid][1];
        out[tid] = e->l2i[tid] - inter / (e->nfg[tid] * e->nfg[tid]);
    }
}

// ---------------------------------------------------------------------------
extern "C" void kernel_launch(void* const* d_in, const int* in_sizes, int n_in,
                              void* d_out, int out_size) {
    const float* emb   = (const float*)d_in[0];   // (4,32,128,128) f32
    const int*   label = (const int*)d_in[1];     // (4,512,512) int32
    float*       out   = (float*)d_out;           // (4,) f32

    prep_kernel<<<dim3(IN_W / 32, IN_H, NB), dim3(32, 32)>>>(emb, label);
    main_kernel<<<GRID_MAIN, 256>>>(label, out);
}